// round 15
// baseline (speedup 1.0000x reference)
#include <cuda_runtime.h>
#include <cuda_fp16.h>
#include <cstdint>

// ============================================================================
// BBoxHead as one fp16 legacy-HMMA GEMM (mma.sync.m16n8k16; compute_103 target
// has no tcgen05). C[8192,448] = A[8192,12544] x W[448,12544]^T, fp32 acc.
//   cols 0..80   -> cls head (+b_cls):  out[m*81 + n]
//   cols 81..404 -> reg head (+b_reg):  out[8192*81 + m*324 + (n-81)]
//   cols 405..447 = zero pad (discarded)
// Round-15 vs round-11 (best, 234us): same inner loop (8 warps, double-buffered
// fragments, 3->4 stage mbarrier full/empty pipeline, XOR-8 swizzle), but tile
// shape BM=64xBN=448 -> BM=128xBN=224 (grid 64x2): per-chunk smem writes drop
// 64KB->44KB and cp.async issue count halves (14->7/thread), at the cost of
// reading A twice from DRAM (822MB ~= 103us floor, still under compute).
// Cross-chunk fragment prefetch abandoned (r13/r14 both regressed).
// ============================================================================

#define KDIM  12544
#define MDIM  8192
#define NCLS  81
#define NREG  324
#define NTOT  405
#define BM    128
#define BN    224
#define BK    64
#define NCHUNK 196            // 12544 / 64
#define NSTAGE 4
#define NTHREADS 256

#define A_STAGE 16384         // 128 rows x 128B
#define B_STAGE 28672         // 224 rows x 128B
#define OFF_BIAS 0            // 224 * 4 = 896B
#define OFF_MBAR 1024         // 8 mbarriers x 8B
#define OFF_A    2048
#define OFF_B    (OFF_A + NSTAGE * A_STAGE)   // 67584
#define SMEM_TOTAL (OFF_B + NSTAGE * B_STAGE) // 182272

__device__ __half g_Wh[(size_t)448 * KDIM];   // fp16 W scratch (448 rows, >=405 zeroed)

// ---------------- helpers ----------------
__device__ __forceinline__ uint32_t smem_u32(const void* p) {
    uint32_t a;
    asm("{ .reg .u64 t; cvta.to.shared.u64 t, %1; cvt.u32.u64 %0, t; }" : "=r"(a) : "l"(p));
    return a;
}
// 128B rows, 8 x 16B chunks per row; chunk XOR row&7 keeps both the 16B store
// phases and all ldmatrix read phases bank-conflict-free (validated r6/r10/r11).
__device__ __forceinline__ uint32_t swz8(uint32_t row, uint32_t q) {
    return row * 128u + ((q ^ (row & 7u)) << 4);
}
__device__ __forceinline__ void cpa16(uint32_t dst, const void* src) {
    asm volatile("cp.async.cg.shared.global [%0], [%1], 16;" :: "r"(dst), "l"(src) : "memory");
}
__device__ __forceinline__ void mbar_init(uint32_t mbar, uint32_t cnt) {
    asm volatile("mbarrier.init.shared.b64 [%0], %1;" :: "r"(mbar), "r"(cnt) : "memory");
}
__device__ __forceinline__ void mbar_arrive(uint32_t mbar) {
    asm volatile("mbarrier.arrive.shared.b64 _, [%0];" :: "r"(mbar) : "memory");
}
// .noinc: consumes one pre-initialized arrival slot on async completion.
__device__ __forceinline__ void cp_arrive_noinc(uint32_t mbar) {
    asm volatile("cp.async.mbarrier.arrive.noinc.shared::cta.b64 [%0];" :: "r"(mbar) : "memory");
}
__device__ __forceinline__ void mbar_wait(uint32_t mbar, uint32_t phase) {
    asm volatile(
        "{\n\t.reg .pred P;\n\t"
        "W%=:\n\t"
        "mbarrier.try_wait.parity.acquire.cta.shared::cta.b64 P, [%0], %1, 0x989680;\n\t"
        "@!P bra W%=;\n\t}"
        :: "r"(mbar), "r"(phase) : "memory");
}
__device__ __forceinline__ void ldsm4(uint32_t* r, uint32_t addr) {
    asm volatile("ldmatrix.sync.aligned.m8n8.x4.shared.b16 {%0,%1,%2,%3}, [%4];"
        : "=r"(r[0]), "=r"(r[1]), "=r"(r[2]), "=r"(r[3]) : "r"(addr));
}
__device__ __forceinline__ void ldsm2(uint32_t* r, uint32_t addr) {
    asm volatile("ldmatrix.sync.aligned.m8n8.x2.shared.b16 {%0,%1}, [%2];"
        : "=r"(r[0]), "=r"(r[1]) : "r"(addr));
}
__device__ __forceinline__ void mma16816(float* c, const uint32_t* a, const uint32_t* b) {
    asm volatile(
        "mma.sync.aligned.m16n8k16.row.col.f32.f16.f16.f32 "
        "{%0,%1,%2,%3}, {%4,%5,%6,%7}, {%8,%9}, {%0,%1,%2,%3};"
        : "+f"(c[0]), "+f"(c[1]), "+f"(c[2]), "+f"(c[3])
        : "r"(a[0]), "r"(a[1]), "r"(a[2]), "r"(a[3]), "r"(b[0]), "r"(b[1]));
}
__device__ __forceinline__ uint32_t packh2(float lo, float hi) {
    uint32_t r;
    asm("cvt.rn.f16x2.f32 %0, %1, %2;" : "=r"(r) : "f"(hi), "f"(lo));
    return r;
}

// ---------------- W fp32 -> fp16 pre-kernel (rows >= 405 zeroed) ----------------
__global__ void wconv_kernel(const float* __restrict__ Wc, const float* __restrict__ Wr) {
    int row = blockIdx.y;
    int col = (blockIdx.x * 256 + threadIdx.x) * 4;
    if (col >= KDIM) return;
    float4 v = make_float4(0.f, 0.f, 0.f, 0.f);
    if (row < NCLS)      v = *reinterpret_cast<const float4*>(Wc + (size_t)row * KDIM + col);
    else if (row < NTOT) v = *reinterpret_cast<const float4*>(Wr + (size_t)(row - NCLS) * KDIM + col);
    *reinterpret_cast<uint2*>(&g_Wh[(size_t)row * KDIM + col]) =
        make_uint2(packh2(v.x, v.y), packh2(v.z, v.w));
}

// ---------------- main GEMM kernel ----------------
__global__ __launch_bounds__(NTHREADS, 1)
void bbox_head_mma(const float* __restrict__ A,
                   const float* __restrict__ bc,
                   const float* __restrict__ br,
                   float* __restrict__ out)
{
    extern __shared__ char smem[];
    const uint32_t sb = smem_u32(smem);
    const int tid   = threadIdx.x;
    const int lane  = tid & 31;
    const int wid   = tid >> 5;
    const int warpM = wid & 1;          // 0..1 (64-row halves of BM=128)
    const int warpN = wid >> 1;         // 0..3 (56-col slices of BN=224)
    const int mBlock = blockIdx.x * BM;
    const int nBase  = blockIdx.y * BN; // 0 or 224
    float* bias_sm = reinterpret_cast<float*>(smem + OFF_BIAS);

#define FULLB(s)  (sb + OFF_MBAR + (s) * 8)
#define EMPTYB(s) (sb + OFF_MBAR + NSTAGE * 8 + (s) * 8)

    if (tid == 0) {
        #pragma unroll
        for (int s = 0; s < NSTAGE; s++) {
            mbar_init(FULLB(s), 2 * NTHREADS);  // 256 STS-arrives + 256 noinc cp-arrives
            mbar_init(EMPTYB(s), NTHREADS);
        }
    }
    for (int j = tid; j < BN; j += NTHREADS) {
        int n = nBase + j;
        bias_sm[j] = (n < NCLS) ? bc[n] : ((n < NTOT) ? br[n - NCLS] : 0.f);
    }
    __syncthreads();

    // A loader: thread owns row ar=tid>>1 (0..127), 16B chunks aq0..aq0+3
    const int ar  = tid >> 1;           // 0..127
    const int aq0 = (tid & 1) * 4;      // 0 or 4
    float4 abuf[8];

    float acc[4][7][4];
    #pragma unroll
    for (int i = 0; i < 4; i++)
        #pragma unroll
        for (int j = 0; j < 7; j++)
            #pragma unroll
            for (int v = 0; v < 4; v++) acc[i][j][v] = 0.f;

#define LDG_A(K0) do { \
        const float* _p = A + (size_t)(mBlock + ar) * KDIM + (K0) + aq0 * 8; \
        _Pragma("unroll") \
        for (int _i = 0; _i < 8; _i++) \
            abuf[_i] = *reinterpret_cast<const float4*>(_p + _i * 4); } while (0)

#define STS_A(S) do { \
        _Pragma("unroll") \
        for (int _i = 0; _i < 4; _i++) { \
            uint4 _v = make_uint4( \
                packh2(abuf[2*_i].x,   abuf[2*_i].y),   packh2(abuf[2*_i].z,   abuf[2*_i].w), \
                packh2(abuf[2*_i+1].x, abuf[2*_i+1].y), packh2(abuf[2*_i+1].z, abuf[2*_i+1].w)); \
            *reinterpret_cast<uint4*>(smem + OFF_A + (S) * A_STAGE + swz8(ar, aq0 + _i)) = _v; } } while (0)

#define CP_B(K0, S) do { \
        _Pragma("unroll") \
        for (int _i = 0; _i < 7; _i++) { \
            int _idx = tid + _i * NTHREADS; /* 0..1791 = 224 rows x 8 chunks */ \
            int _row = _idx >> 3, _q = _idx & 7; \
            cpa16(sb + OFF_B + (S) * B_STAGE + swz8(_row, _q), \
                  g_Wh + (size_t)(nBase + _row) * KDIM + (K0) + _q * 8); } } while (0)

    // fragment load for one kt (0..3) into given buffers
#define LOAD_FRAGS(KT, AF, BF) do { \
        _Pragma("unroll") \
        for (int _m = 0; _m < 4; _m++) { \
            uint32_t _row = warpM * 64 + _m * 16 + ((lane >> 3) & 1) * 8 + (lane & 7); \
            uint32_t _q   = (KT) * 2 + (lane >> 4); \
            ldsm4((AF)[_m], aS + swz8(_row, _q)); } \
        _Pragma("unroll") \
        for (int _p = 0; _p < 3; _p++) { \
            uint32_t _row = warpN * 56 + _p * 16 + (lane >> 4) * 8 + (lane & 7); \
            uint32_t _q   = (KT) * 2 + ((lane >> 3) & 1); \
            uint32_t _r4[4]; \
            ldsm4(_r4, bS + swz8(_row, _q)); \
            (BF)[2 * _p][0] = _r4[0]; (BF)[2 * _p][1] = _r4[1]; \
            (BF)[2 * _p + 1][0] = _r4[2]; (BF)[2 * _p + 1][1] = _r4[3]; } \
        { uint32_t _row = warpN * 56 + 48 + (lane & 7); \
          uint32_t _q   = (KT) * 2 + ((lane >> 3) & 1); \
          ldsm2((BF)[6], bS + swz8(_row, _q)); } } while (0)

    // ---- prologue: produce stages 0,1 (chunks 0,1); hold chunk 2's A ----
    LDG_A(0);
    STS_A(0); CP_B(0, 0); mbar_arrive(FULLB(0)); cp_arrive_noinc(FULLB(0));
    LDG_A(BK);
    STS_A(1); CP_B(BK, 1); mbar_arrive(FULLB(1)); cp_arrive_noinc(FULLB(1));
    LDG_A(2 * BK);

    // ---- main loop: consume chunk k (double-buffered frags), produce k+2 ----
    for (int k = 0; k < NCHUNK; k++) {
        const int sc = k % NSTAGE;
        mbar_wait(FULLB(sc), (uint32_t)((k / NSTAGE) & 1));

        const uint32_t aS = sb + OFF_A + sc * A_STAGE;
        const uint32_t bS = sb + OFF_B + sc * B_STAGE;

        uint32_t afrag[2][4][4];
        uint32_t bfrag[2][7][2];
        LOAD_FRAGS(0, afrag[0], bfrag[0]);
        #pragma unroll
        for (int kt = 0; kt < 4; kt++) {
            const int cur = kt & 1, nxt = cur ^ 1;
            if (kt < 3) LOAD_FRAGS(kt + 1, afrag[nxt], bfrag[nxt]);
            #pragma unroll
            for (int mi = 0; mi < 4; mi++)
                #pragma unroll
                for (int ni = 0; ni < 7; ni++)
                    mma16816(acc[mi][ni], afrag[cur][mi], bfrag[cur][ni]);
        }
        mbar_arrive(EMPTYB(sc));

        const int j = k + 2;
        if (j < NCHUNK) {
            const int sp = j % NSTAGE;
            // fresh stages (j/NSTAGE==0) pass immediately on parity 1
            mbar_wait(EMPTYB(sp), (uint32_t)(((j / NSTAGE) & 1) ^ 1));
            STS_A(sp);
            CP_B(j * BK, sp);
            mbar_arrive(FULLB(sp));        // release for the STS
            cp_arrive_noinc(FULLB(sp));    // fires when this thread's cp.asyncs land
            if (j + 1 < NCHUNK) LDG_A((j + 1) * BK);
        }
    }

    // ---- epilogue: bias + split store ----
    const size_t regBase = (size_t)MDIM * NCLS;
    #pragma unroll
    for (int mi = 0; mi < 4; mi++) {
        #pragma unroll
        for (int ni = 0; ni < 7; ni++) {
            int m0  = mBlock + warpM * 64 + mi * 16 + (lane >> 2);
            int nl0 = warpN * 56 + ni * 8 + (lane & 3) * 2;
            #pragma unroll
            for (int v = 0; v < 4; v++) {
                int m  = m0 + (v >> 1) * 8;
                int nl = nl0 + (v & 1);
                int n  = nBase + nl;
                if (n >= NTOT) continue;
                float val = acc[mi][ni][v] + bias_sm[nl];
                if (n < NCLS) out[(size_t)m * NCLS + n] = val;
                else          out[regBase + (size_t)m * NREG + (n - NCLS)] = val;
            }
        }
    }
}

extern "C" void kernel_launch(void* const* d_in, const int* in_sizes, int n_in,
                              void* d_out, int out_size)
{
    const float* x  = (const float*)d_in[0];
    const float* Wc = (const float*)d_in[1];
    const float* bc = (const float*)d_in[2];
    const float* Wr = (const float*)d_in[3];
    const float* br = (const float*)d_in[4];
    float* out = (float*)d_out;

    cudaFuncSetAttribute(bbox_head_mma, cudaFuncAttributeMaxDynamicSharedMemorySize, SMEM_TOTAL);

    dim3 wgrid((KDIM / 4 + 255) / 256, 448);
    wconv_kernel<<<wgrid, 256>>>(Wc, Wr);

    dim3 grid(MDIM / BM, 2);            // 64 x 2 = 128 CTAs
    bbox_head_mma<<<grid, NTHREADS, SMEM_TOTAL>>>(x, bc, br, out);
}

// round 16
// speedup vs baseline: 1.4924x; 1.4924x over previous
#include <cuda_runtime.h>
#include <cuda_fp16.h>
#include <cstdint>

// ============================================================================
// BBoxHead as one fp16 legacy-HMMA GEMM (mma.sync.m16n8k16; compute_103 target
// has no tcgen05). C[8192,448] = A[8192,12544] x W[448,12544]^T, fp32 acc.
//   cols 0..80   -> cls head (+b_cls):  out[m*81 + n]
//   cols 81..404 -> reg head (+b_reg):  out[8192*81 + m*324 + (n-81)]
//   cols 405..447 = zero pad (discarded)
// Round-16 = round-11 (best, 234us) + ONE isolated change: EARLY EMPTY ARRIVE.
// The last smem read of stage sc is LOAD_FRAGS(3), issued during kt=2; the
// EMPTY(sc) arrive moves there (release semantics order the prior LDSM reads),
// signalling ~2 MMA-groups earlier and shrinking the producer-side rendezvous
// on the slowest warp. Micro: CP_B issued before STS_A in the produce phase.
// r12/r13/r14/r15 perturbations all regressed -> r11 is a sharp optimum;
// this is a minimal single-variable probe of the rendezvous term.
// ============================================================================

#define KDIM  12544
#define MDIM  8192
#define NCLS  81
#define NREG  324
#define NTOT  405
#define NPAD  448
#define BM    64
#define BK    64
#define NCHUNK 196            // 12544 / 64
#define NSTAGE 3
#define NTHREADS 256

#define A_STAGE 8192          // 64 rows x 128B
#define B_STAGE 57344         // 448 rows x 128B
#define OFF_BIAS 0            // 448 * 4 = 1792B
#define OFF_MBAR 1792         // 6 mbarriers x 8B
#define OFF_A    2048
#define OFF_B    (OFF_A + NSTAGE * A_STAGE)   // 26624
#define SMEM_TOTAL (OFF_B + NSTAGE * B_STAGE) // 198656

__device__ __half g_Wh[(size_t)NPAD * KDIM];  // 11.2 MB fp16 W scratch

// ---------------- helpers ----------------
__device__ __forceinline__ uint32_t smem_u32(const void* p) {
    uint32_t a;
    asm("{ .reg .u64 t; cvta.to.shared.u64 t, %1; cvt.u32.u64 %0, t; }" : "=r"(a) : "l"(p));
    return a;
}
// 128B rows, 8 x 16B chunks per row; chunk XOR row&7 keeps both the 16B store
// phases and all ldmatrix read phases bank-conflict-free (validated r6/r10/r11).
__device__ __forceinline__ uint32_t swz8(uint32_t row, uint32_t q) {
    return row * 128u + ((q ^ (row & 7u)) << 4);
}
__device__ __forceinline__ void cpa16(uint32_t dst, const void* src) {
    asm volatile("cp.async.cg.shared.global [%0], [%1], 16;" :: "r"(dst), "l"(src) : "memory");
}
__device__ __forceinline__ void mbar_init(uint32_t mbar, uint32_t cnt) {
    asm volatile("mbarrier.init.shared.b64 [%0], %1;" :: "r"(mbar), "r"(cnt) : "memory");
}
__device__ __forceinline__ void mbar_arrive(uint32_t mbar) {
    asm volatile("mbarrier.arrive.shared.b64 _, [%0];" :: "r"(mbar) : "memory");
}
// .noinc: consumes one pre-initialized arrival slot on async completion.
__device__ __forceinline__ void cp_arrive_noinc(uint32_t mbar) {
    asm volatile("cp.async.mbarrier.arrive.noinc.shared::cta.b64 [%0];" :: "r"(mbar) : "memory");
}
__device__ __forceinline__ void mbar_wait(uint32_t mbar, uint32_t phase) {
    asm volatile(
        "{\n\t.reg .pred P;\n\t"
        "W%=:\n\t"
        "mbarrier.try_wait.parity.acquire.cta.shared::cta.b64 P, [%0], %1, 0x989680;\n\t"
        "@!P bra W%=;\n\t}"
        :: "r"(mbar), "r"(phase) : "memory");
}
__device__ __forceinline__ void ldsm4(uint32_t* r, uint32_t addr) {
    asm volatile("ldmatrix.sync.aligned.m8n8.x4.shared.b16 {%0,%1,%2,%3}, [%4];"
        : "=r"(r[0]), "=r"(r[1]), "=r"(r[2]), "=r"(r[3]) : "r"(addr));
}
__device__ __forceinline__ void ldsm2(uint32_t* r, uint32_t addr) {
    asm volatile("ldmatrix.sync.aligned.m8n8.x2.shared.b16 {%0,%1}, [%2];"
        : "=r"(r[0]), "=r"(r[1]) : "r"(addr));
}
__device__ __forceinline__ void mma16816(float* c, const uint32_t* a, const uint32_t* b) {
    asm volatile(
        "mma.sync.aligned.m16n8k16.row.col.f32.f16.f16.f32 "
        "{%0,%1,%2,%3}, {%4,%5,%6,%7}, {%8,%9}, {%0,%1,%2,%3};"
        : "+f"(c[0]), "+f"(c[1]), "+f"(c[2]), "+f"(c[3])
        : "r"(a[0]), "r"(a[1]), "r"(a[2]), "r"(a[3]), "r"(b[0]), "r"(b[1]));
}
__device__ __forceinline__ uint32_t packh2(float lo, float hi) {
    uint32_t r;
    asm("cvt.rn.f16x2.f32 %0, %1, %2;" : "=r"(r) : "f"(hi), "f"(lo));
    return r;
}

// ---------------- W fp32 -> fp16 pre-kernel (rows >= 405 zeroed) ----------------
__global__ void wconv_kernel(const float* __restrict__ Wc, const float* __restrict__ Wr) {
    int row = blockIdx.y;
    int col = (blockIdx.x * 256 + threadIdx.x) * 4;
    if (col >= KDIM) return;
    float4 v = make_float4(0.f, 0.f, 0.f, 0.f);
    if (row < NCLS)      v = *reinterpret_cast<const float4*>(Wc + (size_t)row * KDIM + col);
    else if (row < NTOT) v = *reinterpret_cast<const float4*>(Wr + (size_t)(row - NCLS) * KDIM + col);
    *reinterpret_cast<uint2*>(&g_Wh[(size_t)row * KDIM + col]) =
        make_uint2(packh2(v.x, v.y), packh2(v.z, v.w));
}

// ---------------- main GEMM kernel ----------------
__global__ __launch_bounds__(NTHREADS, 1)
void bbox_head_mma(const float* __restrict__ A,
                   const float* __restrict__ bc,
                   const float* __restrict__ br,
                   float* __restrict__ out)
{
    extern __shared__ char smem[];
    const uint32_t sb = smem_u32(smem);
    const int tid   = threadIdx.x;
    const int lane  = tid & 31;
    const int warpN = tid >> 5;         // 0..7, 56-col slice of NPAD=448
    const int mBlock = blockIdx.x * BM;
    float* bias_sm = reinterpret_cast<float*>(smem + OFF_BIAS);

#define FULLB(s)  (sb + OFF_MBAR + (s) * 8)
#define EMPTYB(s) (sb + OFF_MBAR + NSTAGE * 8 + (s) * 8)

    if (tid == 0) {
        #pragma unroll
        for (int s = 0; s < NSTAGE; s++) {
            mbar_init(FULLB(s), 2 * NTHREADS);  // 256 STS-arrives + 256 noinc cp-arrives
            mbar_init(EMPTYB(s), NTHREADS);
        }
    }
    for (int j = tid; j < NPAD; j += NTHREADS)
        bias_sm[j] = (j < NCLS) ? bc[j] : ((j < NTOT) ? br[j - NCLS] : 0.f);
    __syncthreads();

    // A loader: thread owns row (tid>>2), 16B chunks aq, aq+1 (aq=(tid&3)*2)
    const int ar = tid >> 2;            // 0..63
    const int aq = (tid & 3) * 2;       // 0,2,4,6
    float4 abuf[4];

    float acc[4][7][4];
    #pragma unroll
    for (int i = 0; i < 4; i++)
        #pragma unroll
        for (int j = 0; j < 7; j++)
            #pragma unroll
            for (int v = 0; v < 4; v++) acc[i][j][v] = 0.f;

#define LDG_A(K0) do { \
        const float* _p = A + (size_t)(mBlock + ar) * KDIM + (K0) + aq * 8; \
        abuf[0] = *reinterpret_cast<const float4*>(_p); \
        abuf[1] = *reinterpret_cast<const float4*>(_p + 4); \
        abuf[2] = *reinterpret_cast<const float4*>(_p + 8); \
        abuf[3] = *reinterpret_cast<const float4*>(_p + 12); } while (0)

#define STS_A(S) do { \
        uint4 _v0 = make_uint4(packh2(abuf[0].x, abuf[0].y), packh2(abuf[0].z, abuf[0].w), \
                               packh2(abuf[1].x, abuf[1].y), packh2(abuf[1].z, abuf[1].w)); \
        uint4 _v1 = make_uint4(packh2(abuf[2].x, abuf[2].y), packh2(abuf[2].z, abuf[2].w), \
                               packh2(abuf[3].x, abuf[3].y), packh2(abuf[3].z, abuf[3].w)); \
        *reinterpret_cast<uint4*>(smem + OFF_A + (S) * A_STAGE + swz8(ar, aq)) = _v0; \
        *reinterpret_cast<uint4*>(smem + OFF_A + (S) * A_STAGE + swz8(ar, aq + 1)) = _v1; } while (0)

#define CP_B(K0, S) do { \
        _Pragma("unroll") \
        for (int _i = 0; _i < 14; _i++) { \
            int _idx = tid + _i * NTHREADS; /* 0..3583 = 448 rows x 8 chunks */ \
            int _row = _idx >> 3, _q = _idx & 7; \
            cpa16(sb + OFF_B + (S) * B_STAGE + swz8(_row, _q), \
                  g_Wh + (size_t)_row * KDIM + (K0) + _q * 8); } } while (0)

    // fragment load for one kt (0..3) into given buffers
#define LOAD_FRAGS(KT, AF, BF) do { \
        _Pragma("unroll") \
        for (int _m = 0; _m < 4; _m++) { \
            uint32_t _row = _m * 16 + ((lane >> 3) & 1) * 8 + (lane & 7); \
            uint32_t _q   = (KT) * 2 + (lane >> 4); \
            ldsm4((AF)[_m], aS + swz8(_row, _q)); } \
        _Pragma("unroll") \
        for (int _p = 0; _p < 3; _p++) { \
            uint32_t _row = warpN * 56 + _p * 16 + (lane >> 4) * 8 + (lane & 7); \
            uint32_t _q   = (KT) * 2 + ((lane >> 3) & 1); \
            uint32_t _r4[4]; \
            ldsm4(_r4, bS + swz8(_row, _q)); \
            (BF)[2 * _p][0] = _r4[0]; (BF)[2 * _p][1] = _r4[1]; \
            (BF)[2 * _p + 1][0] = _r4[2]; (BF)[2 * _p + 1][1] = _r4[3]; } \
        { uint32_t _row = warpN * 56 + 48 + (lane & 7); \
          uint32_t _q   = (KT) * 2 + ((lane >> 3) & 1); \
          ldsm2((BF)[6], bS + swz8(_row, _q)); } } while (0)

    // ---- prologue: produce stages 0,1 (chunks 0,1); hold chunk 2's A ----
    LDG_A(0);
    STS_A(0); CP_B(0, 0); mbar_arrive(FULLB(0)); cp_arrive_noinc(FULLB(0));
    LDG_A(BK);
    STS_A(1); CP_B(BK, 1); mbar_arrive(FULLB(1)); cp_arrive_noinc(FULLB(1));
    LDG_A(2 * BK);

    // ---- main loop: consume chunk k (double-buffered frags), produce k+2 ----
    for (int k = 0; k < NCHUNK; k++) {
        const int sc = k % NSTAGE;
        mbar_wait(FULLB(sc), (uint32_t)((k / NSTAGE) & 1));

        const uint32_t aS = sb + OFF_A + sc * A_STAGE;
        const uint32_t bS = sb + OFF_B + sc * B_STAGE;

        uint32_t afrag[2][4][4];
        uint32_t bfrag[2][7][2];
        LOAD_FRAGS(0, afrag[0], bfrag[0]);
        #pragma unroll
        for (int kt = 0; kt < 4; kt++) {
            const int cur = kt & 1, nxt = cur ^ 1;
            if (kt < 3) LOAD_FRAGS(kt + 1, afrag[nxt], bfrag[nxt]);
            // EARLY EMPTY ARRIVE: after LOAD_FRAGS(3) -- the last smem read of
            // stage sc -- release-order the reads and free the stage ~2 MMA
            // groups earlier than arriving after the kt3 MMAs.
            if (kt == 2) mbar_arrive(EMPTYB(sc));
            #pragma unroll
            for (int mi = 0; mi < 4; mi++)
                #pragma unroll
                for (int ni = 0; ni < 7; ni++)
                    mma16816(acc[mi][ni], afrag[cur][mi], bfrag[cur][ni]);
        }

        const int j = k + 2;
        if (j < NCHUNK) {
            const int sp = j % NSTAGE;
            // fresh stages (j/NSTAGE==0) pass immediately on parity 1
            mbar_wait(EMPTYB(sp), (uint32_t)(((j / NSTAGE) & 1) ^ 1));
            CP_B(j * BK, sp);              // async copies first: in flight early
            cp_arrive_noinc(FULLB(sp));    // fires when this thread's cp.asyncs land
            STS_A(sp);
            mbar_arrive(FULLB(sp));        // release for the STS
            if (j + 1 < NCHUNK) LDG_A((j + 1) * BK);
        }
    }

    // ---- epilogue: bias + split store ----
    const size_t regBase = (size_t)MDIM * NCLS;
    #pragma unroll
    for (int mi = 0; mi < 4; mi++) {
        #pragma unroll
        for (int ni = 0; ni < 7; ni++) {
            int m0 = mBlock + mi * 16 + (lane >> 2);
            int n0 = warpN * 56 + ni * 8 + (lane & 3) * 2;
            #pragma unroll
            for (int v = 0; v < 4; v++) {
                int m = m0 + (v >> 1) * 8;
                int n = n0 + (v & 1);
                if (n >= NTOT) continue;
                float val = acc[mi][ni][v] + bias_sm[n];
                if (n < NCLS) out[(size_t)m * NCLS + n] = val;
                else          out[regBase + (size_t)m * NREG + (n - NCLS)] = val;
            }
        }
    }
}

extern "C" void kernel_launch(void* const* d_in, const int* in_sizes, int n_in,
                              void* d_out, int out_size)
{
    const float* x  = (const float*)d_in[0];
    const float* Wc = (const float*)d_in[1];
    const float* bc = (const float*)d_in[2];
    const float* Wr = (const float*)d_in[3];
    const float* br = (const float*)d_in[4];
    float* out = (float*)d_out;

    cudaFuncSetAttribute(bbox_head_mma, cudaFuncAttributeMaxDynamicSharedMemorySize, SMEM_TOTAL);

    dim3 wgrid((KDIM / 4 + 255) / 256, NPAD);
    wconv_kernel<<<wgrid, 256>>>(Wc, Wr);

    bbox_head_mma<<<MDIM / BM, NTHREADS, SMEM_TOTAL>>>(x, bc, br, out);
}